// round 11
// baseline (speedup 1.0000x reference)
#include <cuda_runtime.h>

// StereoDenoiser: B=8, C=3, H=1024, W=1920, fp32.
//   disp  = clip(depth*128, 0, 128)            [B,H,W]
//   warped_r = bilinear_x(img_r, x = w - disp) (border clamp)
//   warped_l = bilinear_x(img_l, x = w + disp)
//   out_l = (img_l + warped_r)*0.5 ; out_r = (img_r + warped_l)*0.5
// Output buffer: [out_l | out_r], each B*C*H*W floats.
//
// Strategy: one block per (b,h) image row; per-channel staging of both rows
// into a DUPLICATED-PAIR smem array s2[w] = (v[w], v[w+1]) so each bilinear
// tap pair is a single aligned LDS.64 (half the gather instructions/wavefronts
// of the scalar-tap version). Pairs built from the staged float4 + shfl.

#define BATCH 8
#define CH 3
#define HH 1024
#define WW 1920
#define MAXD 128.0f

__global__ __launch_bounds__(480) void stereo_denoise_kernel(
    const float* __restrict__ img_l,
    const float* __restrict__ img_r,
    const float* __restrict__ depth,
    float* __restrict__ out)
{
    __shared__ float2 s2l[WW];   // 15360 B
    __shared__ float2 s2r[WW];   // 15360 B

    const int row  = blockIdx.x;         // b*HH + h
    const int b    = row / HH;
    const int u    = threadIdx.x;        // 0..479
    const int w0   = u * 4;
    const int lane = u & 31;

    // ---- per-pixel warp indices/weights (channel-invariant) ----
    float4 dep = *reinterpret_cast<const float4*>(depth + (size_t)row * WW + w0);
    float d[4] = {dep.x, dep.y, dep.z, dep.w};

    int   i0L[4], i0R[4];
    float fL[4], fR[4];
#pragma unroll
    for (int p = 0; p < 4; ++p) {
        float disp = fminf(fmaxf(d[p] * MAXD, 0.0f), MAXD);
        float xw = (float)(w0 + p);

        float xl = fminf(fmaxf(xw - disp, 0.0f), (float)(WW - 1));
        int i0 = (int)xl;                    // xl >= 0 -> trunc == floor
        fL[p]  = xl - (float)i0;
        i0L[p] = i0;

        float xr = fminf(fmaxf(xw + disp, 0.0f), (float)(WW - 1));
        int j0 = (int)xr;
        fR[p]  = xr - (float)j0;
        i0R[p] = j0;
    }

    const int HW = HH * WW;
    const int N  = BATCH * CH * HW;          // 47,185,920 (fits int32)
    const int plane0 = b * (CH - 1) * HW + row * WW;   // == b*CH*HW + h*WW

#pragma unroll
    for (int c = 0; c < CH; ++c) {
        const int base = plane0 + c * HW;

        if (c) __syncthreads();              // protect smem before overwrite

        // stage rows (coalesced float4 per image)
        float4 lv = *reinterpret_cast<const float4*>(img_l + base + w0);
        float4 rv = *reinterpret_cast<const float4*>(img_r + base + w0);

        // element at w0+4 comes from the next lane's .x (shfl); lane 31 reads
        // it directly (L2 hit) or duplicates at the row end (f==0 there).
        float lx4 = __shfl_down_sync(0xffffffffu, lv.x, 1);
        float rx4 = __shfl_down_sync(0xffffffffu, rv.x, 1);
        if (lane == 31) {
            if (w0 + 4 < WW) {
                lx4 = __ldg(img_l + base + w0 + 4);
                rx4 = __ldg(img_r + base + w0 + 4);
            } else {
                lx4 = lv.w;
                rx4 = rv.w;
            }
        }

        s2l[w0 + 0] = make_float2(lv.x, lv.y);
        s2l[w0 + 1] = make_float2(lv.y, lv.z);
        s2l[w0 + 2] = make_float2(lv.z, lv.w);
        s2l[w0 + 3] = make_float2(lv.w, lx4);
        s2r[w0 + 0] = make_float2(rv.x, rv.y);
        s2r[w0 + 1] = make_float2(rv.y, rv.z);
        s2r[w0 + 2] = make_float2(rv.z, rv.w);
        s2r[w0 + 3] = make_float2(rv.w, rx4);
        __syncthreads();

        float lvv[4] = {lv.x, lv.y, lv.z, lv.w};
        float rvv[4] = {rv.x, rv.y, rv.z, rv.w};

        float ol[4], og[4];
#pragma unroll
        for (int p = 0; p < 4; ++p) {
            float2 tr = s2r[i0L[p]];             // one LDS.64 per tap pair
            float2 tl = s2l[i0R[p]];
            float wr = tr.x * (1.0f - fL[p]) + tr.y * fL[p];
            float wl = tl.x * (1.0f - fR[p]) + tl.y * fR[p];
            ol[p] = (lvv[p] + wr) * 0.5f;
            og[p] = (rvv[p] + wl) * 0.5f;
        }

        *reinterpret_cast<float4*>(out + base + w0) =
            make_float4(ol[0], ol[1], ol[2], ol[3]);
        *reinterpret_cast<float4*>(out + N + base + w0) =
            make_float4(og[0], og[1], og[2], og[3]);
    }
}

extern "C" void kernel_launch(void* const* d_in, const int* in_sizes, int n_in,
                              void* d_out, int out_size) {
    const float* img_l = (const float*)d_in[0];
    const float* img_r = (const float*)d_in[1];
    const float* depth = (const float*)d_in[2];
    float* out = (float*)d_out;

    const int blocks = BATCH * HH;           // one block per image row
    stereo_denoise_kernel<<<blocks, 480>>>(img_l, img_r, depth, out);
}

// round 13
// speedup vs baseline: 1.1259x; 1.1259x over previous
#include <cuda_runtime.h>

// StereoDenoiser: B=8, C=3, H=1024, W=1920, fp32.
//   disp  = clip(depth*128, 0, 128)            [B,H,W]
//   warped_r = bilinear_x(img_r, x = w - disp) (border clamp)
//   warped_l = bilinear_x(img_l, x = w + disp)
//   out_l = (img_l + warped_r)*0.5 ; out_r = (img_r + warped_l)*0.5
// Output buffer: [out_l | out_r], each B*C*H*W floats.
//
// Strategy: one block per (b,h) image row; per-channel smem staging of both
// rows; all gather taps from LDS (r4 champion structure). Index/fraction math
// is RECOMPUTED per channel from the cached depth values so the only
// long-lived state is d[4] — this lets __launch_bounds__(480,3) be met by
// rematerialization instead of spilling, giving 45 warps/SM.

#define BATCH 8
#define CH 3
#define HH 1024
#define WW 1920
#define MAXD 128.0f

__global__ __launch_bounds__(480, 3) void stereo_denoise_kernel(
    const float* __restrict__ img_l,
    const float* __restrict__ img_r,
    const float* __restrict__ depth,
    float* __restrict__ out)
{
    __shared__ float sl[WW];
    __shared__ float sr[WW];

    const int row = blockIdx.x;          // b*HH + h
    const int b   = row / HH;
    const int u   = threadIdx.x;         // 0..479
    const int w0  = u * 4;

    // only long-lived per-pixel state: raw depth (4 regs)
    float4 dep = *reinterpret_cast<const float4*>(depth + (size_t)row * WW + w0);
    float d[4] = {dep.x, dep.y, dep.z, dep.w};

    const int HW = HH * WW;
    const int N  = BATCH * CH * HW;          // 47,185,920 (fits int32)
    const int plane0 = b * (CH - 1) * HW + row * WW;   // == b*CH*HW + h*WW

#pragma unroll
    for (int c = 0; c < CH; ++c) {
        const int base = plane0 + c * HW;

        if (c) __syncthreads();              // protect smem before overwrite

        // stage rows: one float4 per thread per image (coalesced)
        float4 lv = *reinterpret_cast<const float4*>(img_l + base + w0);
        float4 rv = *reinterpret_cast<const float4*>(img_r + base + w0);
        *reinterpret_cast<float4*>(sl + w0) = lv;
        *reinterpret_cast<float4*>(sr + w0) = rv;
        __syncthreads();

        float lvv[4] = {lv.x, lv.y, lv.z, lv.w};
        float rvv[4] = {rv.x, rv.y, rv.z, rv.w};

        float ol[4], og[4];
#pragma unroll
        for (int p = 0; p < 4; ++p) {
            // recompute indices/fractions from d[p] (remat instead of spill)
            float disp = fminf(fmaxf(d[p] * MAXD, 0.0f), MAXD);
            float xw = (float)(w0 + p);

            float xl = fminf(fmaxf(xw - disp, 0.0f), (float)(WW - 1));
            int a0 = (int)xl;                // xl >= 0 -> trunc == floor
            float fl = xl - (float)a0;
            int a1 = min(a0 + 1, WW - 1);

            float xr = fminf(fmaxf(xw + disp, 0.0f), (float)(WW - 1));
            int b0 = (int)xr;
            float fr = xr - (float)b0;
            int b1 = min(b0 + 1, WW - 1);

            float wr = sr[a0] * (1.0f - fl) + sr[a1] * fl;
            float wl = sl[b0] * (1.0f - fr) + sl[b1] * fr;
            ol[p] = (lvv[p] + wr) * 0.5f;
            og[p] = (rvv[p] + wl) * 0.5f;
        }

        *reinterpret_cast<float4*>(out + base + w0) =
            make_float4(ol[0], ol[1], ol[2], ol[3]);
        *reinterpret_cast<float4*>(out + N + base + w0) =
            make_float4(og[0], og[1], og[2], og[3]);
    }
}

extern "C" void kernel_launch(void* const* d_in, const int* in_sizes, int n_in,
                              void* d_out, int out_size) {
    const float* img_l = (const float*)d_in[0];
    const float* img_r = (const float*)d_in[1];
    const float* depth = (const float*)d_in[2];
    float* out = (float*)d_out;

    const int blocks = BATCH * HH;           // one block per image row
    stereo_denoise_kernel<<<blocks, 480>>>(img_l, img_r, depth, out);
}